// round 1
// baseline (speedup 1.0000x reference)
#include <cuda_runtime.h>
#include <cuda_bf16.h>
#include <mma.h>

using namespace nvcuda;

#define BATCH 4
#define CQd   256
#define CKVd  256
#define NQd   2048
#define NKVd  2048
#define NH    8
#define DKd   64
#define ODd   512   // NH*DKd
#define KSPLIT 8

// ---------------- scratch (static device globals; no runtime alloc) -------
__device__ __nv_bfloat16 g_xq [BATCH*CQd*NQd];
__device__ __nv_bfloat16 g_xkv[BATCH*CKVd*NKVd];
__device__ __nv_bfloat16 g_Wq [ODd*CQd];
__device__ __nv_bfloat16 g_Wk [ODd*CKVd];
__device__ __nv_bfloat16 g_Wv [ODd*CKVd];
__device__ __nv_bfloat16 g_Wo [CQd*ODd];
__device__ __nv_bfloat16 g_Q  [BATCH*ODd*NQd];
__device__ __nv_bfloat16 g_K  [BATCH*ODd*NKVd];
__device__ __nv_bfloat16 g_V  [BATCH*ODd*NKVd];
__device__ float         g_Mpart[KSPLIT*BATCH*NH*DKd*DKd];
__device__ __nv_bfloat16 g_M  [BATCH*NH*DKd*DKd];
__device__ __nv_bfloat16 g_A  [BATCH*ODd*NQd];

// ---------------- fp32 -> bf16 conversion ---------------------------------
__global__ void f2bf4_kernel(const float4* __restrict__ src,
                             __nv_bfloat162* __restrict__ dst, int n4) {
    int i = blockIdx.x * blockDim.x + threadIdx.x;
    if (i < n4) {
        float4 v = src[i];
        dst[2*i  ] = __floats2bfloat162_rn(v.x, v.y);
        dst[2*i+1] = __floats2bfloat162_rn(v.z, v.w);
    }
}

// ---------------- generic tiled bf16 GEMM: Y[b] = W(OxC) * X[b](CxN) -------
// FINAL=false: write bf16 to Ybf.  FINAL=true: Yf = gamma*acc + resid (fp32).
template<bool FINAL>
__global__ void gemm_kernel(const __nv_bfloat16* __restrict__ W,
                            const __nv_bfloat16* __restrict__ X,
                            __nv_bfloat16* __restrict__ Ybf,
                            float* __restrict__ Yf,
                            const float* __restrict__ resid,
                            const float* __restrict__ gammap,
                            int O, int Cd, int N) {
    const int n0 = blockIdx.x * 64;
    const int o0 = blockIdx.y * 64;
    const int b  = blockIdx.z;
    const __nv_bfloat16* Xb = X + (size_t)b * Cd * N;

    __shared__ __align__(32) __nv_bfloat16 As[64][40];  // 64 x 32, pad 40
    __shared__ __align__(32) __nv_bfloat16 Bs[32][72];  // 32 x 64, pad 72
    __shared__ __align__(32) float         Cs[64][68];

    const int tid  = threadIdx.x;
    const int warp = tid >> 5;
    const int wr   = warp >> 1;   // 0..1 -> row half
    const int wc   = warp & 1;    // 0..1 -> col half

    wmma::fragment<wmma::accumulator,16,16,16,float> acc[2][2];
    #pragma unroll
    for (int i = 0; i < 2; i++)
        #pragma unroll
        for (int j = 0; j < 2; j++) wmma::fill_fragment(acc[i][j], 0.0f);

    for (int k0 = 0; k0 < Cd; k0 += 32) {
        // stage A tile 64x32 (vectorized 4 bf16 per thread-load)
        #pragma unroll
        for (int t = tid; t < 512; t += 128) {
            int r = t >> 3, c4 = (t & 7) * 4;
            *(uint2*)&As[r][c4] = *(const uint2*)(W + (size_t)(o0 + r) * Cd + k0 + c4);
        }
        // stage B tile 32x64
        #pragma unroll
        for (int t = tid; t < 512; t += 128) {
            int r = t >> 4, c4 = (t & 15) * 4;
            *(uint2*)&Bs[r][c4] = *(const uint2*)(Xb + (size_t)(k0 + r) * N + n0 + c4);
        }
        __syncthreads();

        #pragma unroll
        for (int kk = 0; kk < 32; kk += 16) {
            wmma::fragment<wmma::matrix_a,16,16,16,__nv_bfloat16,wmma::row_major> af[2];
            wmma::fragment<wmma::matrix_b,16,16,16,__nv_bfloat16,wmma::row_major> bf[2];
            #pragma unroll
            for (int i = 0; i < 2; i++)
                wmma::load_matrix_sync(af[i], &As[wr*32 + i*16][kk], 40);
            #pragma unroll
            for (int j = 0; j < 2; j++)
                wmma::load_matrix_sync(bf[j], &Bs[kk][wc*32 + j*16], 72);
            #pragma unroll
            for (int i = 0; i < 2; i++)
                #pragma unroll
                for (int j = 0; j < 2; j++)
                    wmma::mma_sync(acc[i][j], af[i], bf[j], acc[i][j]);
        }
        __syncthreads();
    }

    #pragma unroll
    for (int i = 0; i < 2; i++)
        #pragma unroll
        for (int j = 0; j < 2; j++)
            wmma::store_matrix_sync(&Cs[wr*32 + i*16][wc*32 + j*16], acc[i][j], 68,
                                    wmma::mem_row_major);
    __syncthreads();

    float g = 0.0f;
    if (FINAL) g = gammap[0];
    #pragma unroll
    for (int t = tid; t < 4096; t += 128) {
        int r = t >> 6, c = t & 63;
        size_t idx = (size_t)b * O * N + (size_t)(o0 + r) * N + n0 + c;
        float v = Cs[r][c];
        if (FINAL) Yf[idx] = g * v + resid[idx];
        else       Ybf[idx] = __float2bfloat16(v);
    }
}

// ---------------- M_part[ks,b,h] = K_h(64 x Kslice) * V_h^T ---------------
__global__ void kv_outer_kernel() {
    const int ks = blockIdx.x, h = blockIdx.y, b = blockIdx.z;
    const __nv_bfloat16* Kb = g_K + ((size_t)b * ODd + h * DKd) * NKVd;
    const __nv_bfloat16* Vb = g_V + ((size_t)b * ODd + h * DKd) * NKVd;
    const int warp = threadIdx.x >> 5, wr = warp >> 1, wc = warp & 1;

    wmma::fragment<wmma::accumulator,16,16,16,float> acc[2][2];
    #pragma unroll
    for (int i = 0; i < 2; i++)
        #pragma unroll
        for (int j = 0; j < 2; j++) wmma::fill_fragment(acc[i][j], 0.0f);

    const int k0 = ks * (NKVd / KSPLIT);
    for (int k = k0; k < k0 + NKVd / KSPLIT; k += 16) {
        wmma::fragment<wmma::matrix_a,16,16,16,__nv_bfloat16,wmma::row_major> af[2];
        wmma::fragment<wmma::matrix_b,16,16,16,__nv_bfloat16,wmma::col_major> bf[2];
        #pragma unroll
        for (int i = 0; i < 2; i++)
            wmma::load_matrix_sync(af[i], Kb + (size_t)(wr*32 + i*16) * NKVd + k, NKVd);
        #pragma unroll
        for (int j = 0; j < 2; j++)
            wmma::load_matrix_sync(bf[j], Vb + (size_t)(wc*32 + j*16) * NKVd + k, NKVd);
        #pragma unroll
        for (int i = 0; i < 2; i++)
            #pragma unroll
            for (int j = 0; j < 2; j++)
                wmma::mma_sync(acc[i][j], af[i], bf[j], acc[i][j]);
    }
    float* Mout = g_Mpart + ((size_t)(ks * BATCH + b) * NH + h) * DKd * DKd;
    #pragma unroll
    for (int i = 0; i < 2; i++)
        #pragma unroll
        for (int j = 0; j < 2; j++)
            wmma::store_matrix_sync(Mout + (size_t)(wr*32 + i*16) * DKd + wc*32 + j*16,
                                    acc[i][j], DKd, wmma::mem_row_major);
}

// ---------------- reduce split-K partials, scale 1/DK, -> bf16 ------------
__global__ void reduce_m_kernel() {
    int i = blockIdx.x * blockDim.x + threadIdx.x;
    const int n = BATCH * NH * DKd * DKd;
    if (i < n) {
        float s = 0.0f;
        #pragma unroll
        for (int ks = 0; ks < KSPLIT; ks++) s += g_Mpart[(size_t)ks * n + i];
        g_M[i] = __float2bfloat16(s * (1.0f / DKd));
    }
}

// ---------------- A_h = M_h^T(64x64) * Q_h(64 x N) -------------------------
__global__ void qm_kernel() {
    const int n0 = blockIdx.x * 64;
    const int bh = blockIdx.y;
    const int b = bh >> 3, h = bh & 7;
    const __nv_bfloat16* Mb = g_M + (size_t)bh * DKd * DKd;
    const __nv_bfloat16* Qb = g_Q + ((size_t)b * ODd + h * DKd) * NQd;
    __shared__ __align__(32) float Cs[64][68];

    const int tid = threadIdx.x;
    const int warp = tid >> 5, wr = warp >> 1, wc = warp & 1;

    wmma::fragment<wmma::accumulator,16,16,16,float> acc[2][2];
    #pragma unroll
    for (int i = 0; i < 2; i++)
        #pragma unroll
        for (int j = 0; j < 2; j++) wmma::fill_fragment(acc[i][j], 0.0f);

    #pragma unroll
    for (int kt = 0; kt < 4; kt++) {
        // A = M^T: element (e,d) = M[d*64 + e] -> col_major view of M, ldm 64
        wmma::fragment<wmma::matrix_a,16,16,16,__nv_bfloat16,wmma::col_major> af[2];
        wmma::fragment<wmma::matrix_b,16,16,16,__nv_bfloat16,wmma::row_major> bf[2];
        #pragma unroll
        for (int i = 0; i < 2; i++)
            wmma::load_matrix_sync(af[i], Mb + (size_t)kt * 16 * DKd + wr*32 + i*16, DKd);
        #pragma unroll
        for (int j = 0; j < 2; j++)
            wmma::load_matrix_sync(bf[j], Qb + (size_t)kt * 16 * NQd + n0 + wc*32 + j*16, NQd);
        #pragma unroll
        for (int i = 0; i < 2; i++)
            #pragma unroll
            for (int j = 0; j < 2; j++)
                wmma::mma_sync(acc[i][j], af[i], bf[j], acc[i][j]);
    }
    #pragma unroll
    for (int i = 0; i < 2; i++)
        #pragma unroll
        for (int j = 0; j < 2; j++)
            wmma::store_matrix_sync(&Cs[wr*32 + i*16][wc*32 + j*16], acc[i][j], 68,
                                    wmma::mem_row_major);
    __syncthreads();

    __nv_bfloat16* Ab = g_A + ((size_t)b * ODd + h * DKd) * NQd;
    #pragma unroll
    for (int t = tid; t < 4096; t += 128) {
        int r = t >> 6, c = t & 63;
        Ab[(size_t)r * NQd + n0 + c] = __float2bfloat16(Cs[r][c]);
    }
}

// ---------------------------------------------------------------------------
extern "C" void kernel_launch(void* const* d_in, const int* in_sizes, int n_in,
                              void* d_out, int out_size) {
    const float* xq    = (const float*)d_in[0];
    const float* xkv   = (const float*)d_in[1];
    const float* Wq    = (const float*)d_in[2];
    const float* Wk    = (const float*)d_in[3];
    const float* Wv    = (const float*)d_in[4];
    const float* Wo    = (const float*)d_in[5];
    const float* gamma = (const float*)d_in[6];
    float* out = (float*)d_out;

    void *p_xq, *p_xkv, *p_wq, *p_wk, *p_wv, *p_wo, *p_Q, *p_A;
    cudaGetSymbolAddress(&p_xq,  g_xq);
    cudaGetSymbolAddress(&p_xkv, g_xkv);
    cudaGetSymbolAddress(&p_wq,  g_Wq);
    cudaGetSymbolAddress(&p_wk,  g_Wk);
    cudaGetSymbolAddress(&p_wv,  g_Wv);
    cudaGetSymbolAddress(&p_wo,  g_Wo);
    cudaGetSymbolAddress(&p_Q,   g_Q);
    cudaGetSymbolAddress(&p_A,   g_A);
    void *p_K, *p_V;
    cudaGetSymbolAddress(&p_K, g_K);
    cudaGetSymbolAddress(&p_V, g_V);

    const int nx = BATCH * CQd * NQd;   // 2,097,152
    const int nw = ODd * CQd;           // 131,072

    // convert inputs to bf16
    f2bf4_kernel<<<nx/4/256, 256>>>((const float4*)xq,  (__nv_bfloat162*)p_xq,  nx/4);
    f2bf4_kernel<<<nx/4/256, 256>>>((const float4*)xkv, (__nv_bfloat162*)p_xkv, nx/4);
    f2bf4_kernel<<<nw/4/256, 256>>>((const float4*)Wq,  (__nv_bfloat162*)p_wq,  nw/4);
    f2bf4_kernel<<<nw/4/256, 256>>>((const float4*)Wk,  (__nv_bfloat162*)p_wk,  nw/4);
    f2bf4_kernel<<<nw/4/256, 256>>>((const float4*)Wv,  (__nv_bfloat162*)p_wv,  nw/4);
    f2bf4_kernel<<<nw/4/256, 256>>>((const float4*)Wo,  (__nv_bfloat162*)p_wo,  nw/4);

    // Q/K/V projections
    dim3 gq(NQd/64, ODd/64, BATCH);
    gemm_kernel<false><<<gq, 128>>>((const __nv_bfloat16*)p_wq, (const __nv_bfloat16*)p_xq,
                                    (__nv_bfloat16*)p_Q, nullptr, nullptr, nullptr,
                                    ODd, CQd, NQd);
    gemm_kernel<false><<<gq, 128>>>((const __nv_bfloat16*)p_wk, (const __nv_bfloat16*)p_xkv,
                                    (__nv_bfloat16*)p_K, nullptr, nullptr, nullptr,
                                    ODd, CKVd, NKVd);
    gemm_kernel<false><<<gq, 128>>>((const __nv_bfloat16*)p_wv, (const __nv_bfloat16*)p_xkv,
                                    (__nv_bfloat16*)p_V, nullptr, nullptr, nullptr,
                                    ODd, CKVd, NKVd);

    // M = K^T V (split-K partials), reduce+scale
    kv_outer_kernel<<<dim3(KSPLIT, NH, BATCH), 128>>>();
    reduce_m_kernel<<<(BATCH*NH*DKd*DKd)/256, 256>>>();

    // A = M^T Q
    qm_kernel<<<dim3(NQd/64, BATCH*NH), 128>>>();

    // out = gamma * (Wo @ A) + x_q
    gemm_kernel<true><<<dim3(NQd/64, CQd/64, BATCH), 128>>>(
        (const __nv_bfloat16*)p_wo, (const __nv_bfloat16*)p_A,
        nullptr, out, xq, gamma, CQd, ODd, NQd);
}

// round 3
// speedup vs baseline: 1.9045x; 1.9045x over previous
#include <cuda_runtime.h>
#include <cuda_bf16.h>
#include <mma.h>
#include <cstdint>
#include <cstddef>

using namespace nvcuda;
typedef __nv_bfloat16 bf16;

#define BATCH 4
#define CQd   256
#define NQd   2048
#define NKVd  2048
#define NH    8
#define DKd   64
#define ODd   512   // NH*DKd
#define KSPLIT 8

// ---------------- scratch (static device globals; no runtime alloc) -------
__device__ __align__(16) bf16 g_xq [BATCH*CQd*NQd];
__device__ __align__(16) bf16 g_xkv[BATCH*CQd*NKVd];
__device__ __align__(16) bf16 g_Wq [ODd*CQd];
__device__ __align__(16) bf16 g_Wk [ODd*CQd];
__device__ __align__(16) bf16 g_Wv [ODd*CQd];
__device__ __align__(16) bf16 g_Wo [CQd*ODd];
__device__ __align__(16) bf16 g_Q  [BATCH*ODd*NQd];
__device__ __align__(16) bf16 g_K  [BATCH*ODd*NKVd];
__device__ __align__(16) bf16 g_V  [BATCH*ODd*NKVd];
__device__ __align__(16) float g_Mpart[KSPLIT*BATCH*NH*DKd*DKd];
__device__ __align__(16) bf16 g_M  [BATCH*NH*DKd*DKd];
__device__ __align__(16) bf16 g_Wp [BATCH*CQd*ODd];   // fused Wo @ blockdiag(M^T)

// ---------------- fused fp32 -> bf16 conversion (all 6 tensors) -----------
__global__ void convert_all_kernel(const float* __restrict__ xq,
                                   const float* __restrict__ xkv,
                                   const float* __restrict__ Wq,
                                   const float* __restrict__ Wk,
                                   const float* __restrict__ Wv,
                                   const float* __restrict__ Wo) {
    int i = blockIdx.x * blockDim.x + threadIdx.x;  // float4 index, total 1179648
    const float* src; bf16* dst; int off;
    if (i < 524288)            { src = xq;  dst = g_xq;  off = i; }
    else if (i < 1048576)      { src = xkv; dst = g_xkv; off = i - 524288; }
    else {
        int j = i - 1048576;
        int w = j >> 15;  off = j & 32767;
        src = (w == 0) ? Wq : (w == 1) ? Wk : (w == 2) ? Wv : Wo;
        dst = (w == 0) ? g_Wq : (w == 1) ? g_Wk : (w == 2) ? g_Wv : g_Wo;
    }
    float4 v = ((const float4*)src)[off];
    __nv_bfloat162 two[2] = { __floats2bfloat162_rn(v.x, v.y),
                              __floats2bfloat162_rn(v.z, v.w) };
    *(uint2*)&dst[(size_t)off * 4] = *(uint2*)two;
}

// ---------------- cp.async helpers -----------------------------------------
__device__ __forceinline__ void cpa16(void* dst, const void* src) {
    unsigned int d = (unsigned int)__cvta_generic_to_shared(dst);
    asm volatile("cp.async.cg.shared.global [%0], [%1], 16;\n" :: "r"(d), "l"(src));
}
__device__ __forceinline__ void cpa_commit() {
    asm volatile("cp.async.commit_group;\n" ::);
}

// ---------------- pipelined 128x128x32 bf16 GEMM core ----------------------
// Y(OxN) = W(OxCD) * X(CDxN).  FINAL: Yf = gamma*acc + resid (fp32), else bf16.
// 256 threads, 8 warps (2x4), warp tile 64x32, double-buffered cp.async.
template<int CD>
__device__ __forceinline__ void stage_tiles(const bf16* __restrict__ W,
                                            const bf16* __restrict__ Xb,
                                            bf16* As, bf16* Bs,
                                            int o0, int n0, int k0, int tid) {
    #pragma unroll
    for (int u = 0; u < 2; u++) {             // A: 128x32, 512 16B chunks
        int ch = tid + u * 256;
        int r = ch >> 2, cc = (ch & 3) * 8;
        cpa16(As + r * 40 + cc, W + (size_t)(o0 + r) * CD + k0 + cc);
    }
    #pragma unroll
    for (int u = 0; u < 2; u++) {             // B: 32x128, 512 16B chunks
        int ch = tid + u * 256;
        int r = ch >> 4, cc = (ch & 15) * 8;
        cpa16(Bs + r * 136 + cc, Xb + (size_t)(k0 + r) * NQd + n0 + cc);
    }
    cpa_commit();
}

template<bool FINAL, int CD>
__device__ __forceinline__ void gemm_core(const bf16* __restrict__ W,
                                          const bf16* __restrict__ Xb,
                                          bf16* __restrict__ Ybf,
                                          float* __restrict__ Yf,
                                          const float* __restrict__ resid,
                                          const float* __restrict__ gammap) {
    const int n0 = blockIdx.x * 128;
    const int o0 = blockIdx.y * 128;
    extern __shared__ __align__(16) char smem_raw[];
    bf16*  AsB = (bf16*)smem_raw;              // [2][128*40]  = 20480 B
    bf16*  BsB = (bf16*)(smem_raw + 20480);    // [2][32*136]  = 17408 B
    float* Cs  = (float*)smem_raw;             // [128*132]    = 67584 B (reuse)

    const int tid  = threadIdx.x;
    const int warp = tid >> 5;
    const int wr   = warp >> 2;   // 0..1 (64-row half)
    const int wc   = warp & 3;    // 0..3 (32-col quarter)

    wmma::fragment<wmma::accumulator,16,16,16,float> acc[4][2];
    #pragma unroll
    for (int i = 0; i < 4; i++)
        #pragma unroll
        for (int j = 0; j < 2; j++) wmma::fill_fragment(acc[i][j], 0.0f);

    constexpr int KT = CD / 32;
    stage_tiles<CD>(W, Xb, AsB, BsB, o0, n0, 0, tid);

    for (int kt = 0; kt < KT; kt++) {
        if (kt + 1 < KT) {
            stage_tiles<CD>(W, Xb, AsB + ((kt + 1) & 1) * 128 * 40,
                                    BsB + ((kt + 1) & 1) * 32 * 136,
                            o0, n0, (kt + 1) * 32, tid);
            asm volatile("cp.async.wait_group 1;\n" ::);
        } else {
            asm volatile("cp.async.wait_group 0;\n" ::);
        }
        __syncthreads();

        const bf16* As = AsB + (kt & 1) * 128 * 40;
        const bf16* Bs = BsB + (kt & 1) * 32 * 136;
        #pragma unroll
        for (int ks = 0; ks < 2; ks++) {
            wmma::fragment<wmma::matrix_a,16,16,16,bf16,wmma::row_major> af[4];
            wmma::fragment<wmma::matrix_b,16,16,16,bf16,wmma::row_major> bg[2];
            #pragma unroll
            for (int i = 0; i < 4; i++)
                wmma::load_matrix_sync(af[i], As + (wr*64 + i*16) * 40 + ks*16, 40);
            #pragma unroll
            for (int j = 0; j < 2; j++)
                wmma::load_matrix_sync(bg[j], Bs + (ks*16) * 136 + wc*32 + j*16, 136);
            #pragma unroll
            for (int i = 0; i < 4; i++)
                #pragma unroll
                for (int j = 0; j < 2; j++)
                    wmma::mma_sync(acc[i][j], af[i], bg[j], acc[i][j]);
        }
        __syncthreads();
    }

    // epilogue via Cs (smem reuse is safe: accum is in registers)
    #pragma unroll
    for (int i = 0; i < 4; i++)
        #pragma unroll
        for (int j = 0; j < 2; j++)
            wmma::store_matrix_sync(&Cs[(wr*64 + i*16) * 132 + wc*32 + j*16],
                                    acc[i][j], 132, wmma::mem_row_major);
    __syncthreads();

    float g = 0.0f;
    if (FINAL) g = gammap[0];
    #pragma unroll
    for (int t = tid; t < 4096; t += 256) {    // 128x128 / 4-wide
        int r = t >> 5, c4 = (t & 31) * 4;
        float4 v = *(float4*)&Cs[r * 132 + c4];
        size_t gi = (size_t)(o0 + r) * NQd + n0 + c4;
        if (FINAL) {
            float4 x = *(const float4*)&resid[gi];
            v.x = g * v.x + x.x;  v.y = g * v.y + x.y;
            v.z = g * v.z + x.z;  v.w = g * v.w + x.w;
            *(float4*)&Yf[gi] = v;
        } else {
            __nv_bfloat162 two[2] = { __floats2bfloat162_rn(v.x, v.y),
                                      __floats2bfloat162_rn(v.z, v.w) };
            *(uint2*)&Ybf[gi] = *(uint2*)two;
        }
    }
}

// ---------------- Q/K/V projections: one launch, z = b*3 + which -----------
struct ProjArgs { const bf16* W[3]; const bf16* X[2]; bf16* Y[3]; };

__global__ void proj_kernel(ProjArgs a) {
    int z = blockIdx.z;
    int which = z % 3, b = z / 3;
    const bf16* W  = a.W[which];
    const bf16* Xb = (which == 0 ? a.X[0] : a.X[1]) + (size_t)b * CQd * NQd;
    bf16*       Yb = a.Y[which] + (size_t)b * ODd * NQd;
    gemm_core<false, CQd>(W, Xb, Yb, nullptr, nullptr, nullptr);
}

// ---------------- final: out = gamma * (W'_b @ Q_b) + x_q ------------------
__global__ void final_kernel(const float* __restrict__ xq,
                             const float* __restrict__ gammap,
                             float* __restrict__ out) {
    int b = blockIdx.z;
    gemm_core<true, ODd>(g_Wp + (size_t)b * CQd * ODd,
                         g_Q  + (size_t)b * ODd * NQd,
                         nullptr,
                         out + (size_t)b * CQd * NQd,
                         xq  + (size_t)b * CQd * NQd,
                         gammap);
}

// ---------------- M_part[ks,b,h] = K_h(64 x Kslice) * V_h^T ----------------
__global__ void kv_outer_kernel() {
    const int ks = blockIdx.x, h = blockIdx.y, b = blockIdx.z;
    const bf16* Kb = g_K + ((size_t)b * ODd + h * DKd) * NKVd;
    const bf16* Vb = g_V + ((size_t)b * ODd + h * DKd) * NKVd;
    const int warp = threadIdx.x >> 5, wr = warp >> 1, wc = warp & 1;

    wmma::fragment<wmma::accumulator,16,16,16,float> acc[2][2];
    #pragma unroll
    for (int i = 0; i < 2; i++)
        #pragma unroll
        for (int j = 0; j < 2; j++) wmma::fill_fragment(acc[i][j], 0.0f);

    const int k0 = ks * (NKVd / KSPLIT);
    for (int k = k0; k < k0 + NKVd / KSPLIT; k += 16) {
        wmma::fragment<wmma::matrix_a,16,16,16,bf16,wmma::row_major> af[2];
        wmma::fragment<wmma::matrix_b,16,16,16,bf16,wmma::col_major> bg[2];
        #pragma unroll
        for (int i = 0; i < 2; i++)
            wmma::load_matrix_sync(af[i], Kb + (size_t)(wr*32 + i*16) * NKVd + k, NKVd);
        #pragma unroll
        for (int j = 0; j < 2; j++)
            wmma::load_matrix_sync(bg[j], Vb + (size_t)(wc*32 + j*16) * NKVd + k, NKVd);
        #pragma unroll
        for (int i = 0; i < 2; i++)
            #pragma unroll
            for (int j = 0; j < 2; j++)
                wmma::mma_sync(acc[i][j], af[i], bg[j], acc[i][j]);
    }
    float* Mout = g_Mpart + ((size_t)(ks * BATCH + b) * NH + h) * DKd * DKd;
    #pragma unroll
    for (int i = 0; i < 2; i++)
        #pragma unroll
        for (int j = 0; j < 2; j++)
            wmma::store_matrix_sync(Mout + (size_t)(wr*32 + i*16) * DKd + wc*32 + j*16,
                                    acc[i][j], DKd, wmma::mem_row_major);
}

// ---------------- reduce split-K partials, scale 1/DK, -> bf16 -------------
__global__ void reduce_m_kernel() {
    int i = blockIdx.x * blockDim.x + threadIdx.x;
    const int n = BATCH * NH * DKd * DKd;
    if (i < n) {
        float s = 0.0f;
        #pragma unroll
        for (int ks = 0; ks < KSPLIT; ks++) s += g_Mpart[(size_t)ks * n + i];
        g_M[i] = __float2bfloat16(s * (1.0f / DKd));
    }
}

// ---------------- W'_b[c, h*64+d] = sum_e Wo[c, h*64+e] * M~_bh[d,e] -------
__global__ void womt_kernel() {
    const int c0 = blockIdx.x * 64, h = blockIdx.y, b = blockIdx.z;
    const bf16* Mbh = g_M + ((size_t)(b * NH + h)) * DKd * DKd;
    __shared__ __align__(16) float Cs[64][68];
    const int tid = threadIdx.x;
    const int warp = tid >> 5, wr = warp >> 1, wc = warp & 1;

    wmma::fragment<wmma::accumulator,16,16,16,float> acc[2][2];
    #pragma unroll
    for (int i = 0; i < 2; i++)
        #pragma unroll
        for (int j = 0; j < 2; j++) wmma::fill_fragment(acc[i][j], 0.0f);

    #pragma unroll
    for (int kt = 0; kt < 4; kt++) {
        wmma::fragment<wmma::matrix_a,16,16,16,bf16,wmma::row_major> af[2];
        wmma::fragment<wmma::matrix_b,16,16,16,bf16,wmma::col_major> bg[2];
        #pragma unroll
        for (int i = 0; i < 2; i++)
            wmma::load_matrix_sync(af[i],
                g_Wo + (size_t)(c0 + wr*32 + i*16) * ODd + h * DKd + kt*16, ODd);
        #pragma unroll
        for (int j = 0; j < 2; j++)
            wmma::load_matrix_sync(bg[j],
                Mbh + (size_t)(wc*32 + j*16) * DKd + kt*16, DKd);
        #pragma unroll
        for (int i = 0; i < 2; i++)
            #pragma unroll
            for (int j = 0; j < 2; j++)
                wmma::mma_sync(acc[i][j], af[i], bg[j], acc[i][j]);
    }
    #pragma unroll
    for (int i = 0; i < 2; i++)
        #pragma unroll
        for (int j = 0; j < 2; j++)
            wmma::store_matrix_sync(&Cs[wr*32 + i*16][wc*32 + j*16], acc[i][j], 68,
                                    wmma::mem_row_major);
    __syncthreads();

    bf16* outp = g_Wp + (size_t)b * CQd * ODd;
    #pragma unroll
    for (int t = tid; t < 4096; t += 128) {
        int r = t >> 6, c = t & 63;
        outp[(size_t)(c0 + r) * ODd + h * DKd + c] = __float2bfloat16(Cs[r][c]);
    }
}

// ---------------------------------------------------------------------------
extern "C" void kernel_launch(void* const* d_in, const int* in_sizes, int n_in,
                              void* d_out, int out_size) {
    const float* xq    = (const float*)d_in[0];
    const float* xkv   = (const float*)d_in[1];
    const float* Wq    = (const float*)d_in[2];
    const float* Wk    = (const float*)d_in[3];
    const float* Wv    = (const float*)d_in[4];
    const float* Wo    = (const float*)d_in[5];
    const float* gamma = (const float*)d_in[6];
    float* out = (float*)d_out;

    cudaFuncSetAttribute(proj_kernel,  cudaFuncAttributeMaxDynamicSharedMemorySize, 69632);
    cudaFuncSetAttribute(final_kernel, cudaFuncAttributeMaxDynamicSharedMemorySize, 69632);

    // 1) convert everything to bf16 (one launch)
    convert_all_kernel<<<4608, 256>>>(xq, xkv, Wq, Wk, Wv, Wo);

    // 2) Q/K/V projections (one launch, z = b*3 + which)
    ProjArgs pa;
    void *p;
    cudaGetSymbolAddress(&p, g_Wq);  pa.W[0] = (const bf16*)p;
    cudaGetSymbolAddress(&p, g_Wk);  pa.W[1] = (const bf16*)p;
    cudaGetSymbolAddress(&p, g_Wv);  pa.W[2] = (const bf16*)p;
    cudaGetSymbolAddress(&p, g_xq);  pa.X[0] = (const bf16*)p;
    cudaGetSymbolAddress(&p, g_xkv); pa.X[1] = (const bf16*)p;
    cudaGetSymbolAddress(&p, g_Q);   pa.Y[0] = (bf16*)p;
    cudaGetSymbolAddress(&p, g_K);   pa.Y[1] = (bf16*)p;
    cudaGetSymbolAddress(&p, g_V);   pa.Y[2] = (bf16*)p;
    proj_kernel<<<dim3(NQd/128, ODd/128, BATCH*3), 256, 67584>>>(pa);

    // 3) M = (K^T V)/dk  (split-K + reduce)
    kv_outer_kernel<<<dim3(KSPLIT, NH, BATCH), 128>>>();
    reduce_m_kernel<<<(BATCH*NH*DKd*DKd + 255)/256, 256>>>();

    // 4) W'_b = Wo @ blockdiag(M_b^T)   (folds the whole attention apply)
    womt_kernel<<<dim3(CQd/64, NH, BATCH), 128>>>();

    // 5) out = gamma * (W'_b @ Q_b) + x_q
    final_kernel<<<dim3(NQd/128, CQd/128, BATCH), 256, 67584>>>(xq, gamma, out);
}